// round 13
// baseline (speedup 1.0000x reference)
#include <cuda_runtime.h>
#include <cuda_fp16.h>
#include <math.h>
#include <stdint.h>

#define BB 2
#define SS 2048
#define HH 16
#define NOPE 128
#define ROPE 64
#define VD 128
#define DQK 192           // NOPE + ROPE
#define QR 1536
#define KVR 512
#define NQ (HH*DQK)       // 3072
#define NKV (HH*(NOPE+VD))// 4096
#define MM (BB*SS)        // 4096
#define SCALE 0.07216878364870323f  // 1/sqrt(192)

// pure fp16 storage
__device__ __align__(256) unsigned short g_qh[(size_t)BB*HH*SS*DQK];   // [b,h,s,192]
__device__ __align__(256) unsigned short g_kh[(size_t)BB*HH*SS*DQK];   // [b,h,s,192]
__device__ __align__(256) unsigned short g_vth[(size_t)BB*HH*VD*SS];   // [b,h,d,s]
__device__ __align__(256) unsigned short g_qs_h[(size_t)MM*QR];
__device__ __align__(256) unsigned short g_kvs_h[(size_t)MM*KVR];
__device__ __align__(256) unsigned short g_wuq_h[(size_t)NQ*QR];
__device__ __align__(256) unsigned short g_wukv_h[(size_t)NKV*KVR];

// ---------------------------------------------------------------------------
// helpers
// ---------------------------------------------------------------------------
__device__ __forceinline__ uint32_t smem_u32(const void* p) {
    uint32_t a;
    asm("{ .reg .u64 t; cvta.to.shared.u64 t, %1; cvt.u32.u64 %0, t; }" : "=r"(a) : "l"(p));
    return a;
}
__device__ __forceinline__ void ldsm4(uint32_t* r, uint32_t addr) {
    asm volatile("ldmatrix.sync.aligned.m8n8.x4.shared.b16 {%0,%1,%2,%3}, [%4];"
                 : "=r"(r[0]), "=r"(r[1]), "=r"(r[2]), "=r"(r[3]) : "r"(addr));
}
__device__ __forceinline__ void mma16(float* c, const uint32_t* a, const uint32_t* b) {
    asm volatile("mma.sync.aligned.m16n8k16.row.col.f32.f16.f16.f32 "
                 "{%0,%1,%2,%3}, {%4,%5,%6,%7}, {%8,%9}, {%0,%1,%2,%3};"
                 : "+f"(c[0]), "+f"(c[1]), "+f"(c[2]), "+f"(c[3])
                 : "r"(a[0]), "r"(a[1]), "r"(a[2]), "r"(a[3]), "r"(b[0]), "r"(b[1]));
}
__device__ __forceinline__ void cpasync16(uint32_t sdst, const void* gsrc) {
    asm volatile("cp.async.cg.shared.global [%0], [%1], 16;" :: "r"(sdst), "l"(gsrc));
}
#define CP_COMMIT() asm volatile("cp.async.commit_group;" ::: "memory")
#define CP_WAIT(N)  asm volatile("cp.async.wait_group %0;" :: "n"(N) : "memory")

__device__ __forceinline__ uint32_t pack2(float x, float y) {
    __half2 h = __floats2half2_rn(x, y);
    return *(uint32_t*)&h;
}

// ---------------------------------------------------------------------------
// presplit: float -> fp16 (hi only)
// ---------------------------------------------------------------------------
template<int WHICH>
__global__ void presplit_kernel(const float* __restrict__ src, int n4) {
    int i = blockIdx.x * blockDim.x + threadIdx.x;
    if (i >= n4) return;
    unsigned short* H = (WHICH == 0) ? g_qs_h : (WHICH == 1) ? g_kvs_h
                      : (WHICH == 2) ? g_wuq_h : g_wukv_h;
    float4 v = ((const float4*)src)[i];
    ushort4 hh;
    hh.x = __half_as_ushort(__float2half_rn(v.x));
    hh.y = __half_as_ushort(__float2half_rn(v.y));
    hh.z = __half_as_ushort(__float2half_rn(v.z));
    hh.w = __half_as_ushort(__float2half_rn(v.w));
    ((ushort4*)H)[i] = hh;
}

// ---------------------------------------------------------------------------
// GEMM (pure fp16): CTA 128x128, 512 thr (16 warps 4m x 4n), Kc=32,
// 2-stage cp.async pipeline.
// ---------------------------------------------------------------------------
#define GP 40
#define GTILE (128*GP)
#define GSTAGE (2*GTILE*2)
#define GSMEM_TOTAL (2*GSTAGE)

extern __shared__ char gsm[];

template<int MODE>
__global__ __launch_bounds__(512) void gemm_mma_kernel() {
    const unsigned short* Ah = (MODE == 0) ? g_qs_h : g_kvs_h;
    const unsigned short* Wh = (MODE == 0) ? g_wuq_h : g_wukv_h;
    const int K = (MODE == 0) ? QR : KVR;

    const int tid = threadIdx.x;
    const int w = tid >> 5, lane = tid & 31;
    const int g = lane >> 2, t = lane & 3;
    const int lrow = lane & 15, lc8 = (lane >> 4) << 3;
    const int bm = blockIdx.y * 128, bn = blockIdx.x * 128;
    const int mw = (w >> 2) * 32, nw = (w & 3) * 32;
    const uint32_t uS = smem_u32(gsm);

    const int rcp = tid >> 2, scp = tid & 3;
    const uint32_t doff = (uint32_t)((rcp * GP + scp * 8) * 2);

    auto issue_stage = [&](int s, int k0) {
        const uint32_t base = uS + s * GSTAGE;
        cpasync16(base + doff,             Ah + (size_t)(bm + rcp) * K + k0 + scp * 8);
        cpasync16(base + GTILE * 2 + doff, Wh + (size_t)(bn + rcp) * K + k0 + scp * 8);
    };

    float c[2][4][4] = {};
    issue_stage(0, 0);
    CP_COMMIT();

    const int nc = K >> 5;
    for (int cc = 0; cc < nc; cc++) {
        const int s = cc & 1;
        if (cc + 1 < nc) {
            issue_stage(s ^ 1, (cc + 1) << 5);
            CP_COMMIT();
            CP_WAIT(1);
        } else {
            CP_WAIT(0);
        }
        __syncthreads();

        const uint32_t uAh = uS + s * GSTAGE;
        const uint32_t uWh = uAh + GTILE * 2;
#pragma unroll
        for (int kk = 0; kk < 2; kk++) {
            const int kb = kk << 4;
            uint32_t ah[2][4];
#pragma unroll
            for (int mf = 0; mf < 2; mf++) {
                uint32_t off = (uint32_t)(((mw + mf * 16 + lrow) * GP + kb + lc8) * 2);
                ldsm4(ah[mf], uAh + off);
            }
#pragma unroll
            for (int p = 0; p < 2; p++) {
                uint32_t off = (uint32_t)(((nw + p * 16 + lrow) * GP + kb + lc8) * 2);
                uint32_t b4h[4];
                ldsm4(b4h, uWh + off);
                uint32_t bhe[2] = {b4h[0], b4h[2]}, bho[2] = {b4h[1], b4h[3]};
#pragma unroll
                for (int mf = 0; mf < 2; mf++) {
                    mma16(c[mf][2 * p],     ah[mf], bhe);
                    mma16(c[mf][2 * p + 1], ah[mf], bho);
                }
            }
        }
        __syncthreads();
    }

    // epilogue
#pragma unroll
    for (int mf = 0; mf < 2; mf++) {
#pragma unroll
        for (int i = 0; i < 4; i++) {
            const int m = bm + mw + mf * 16 + g + ((i >> 1) << 3);
            const int b = m >> 11, sidx = m & 2047;
#pragma unroll
            for (int nf = 0; nf < 4; nf++) {
                const int n = bn + nw + nf * 8 + (t << 1) + (i & 1);
                const unsigned short hv = __half_as_ushort(__float2half_rn(c[mf][nf][i]));
                if (MODE == 0) {
                    const int h = n / DQK, d = n % DQK;
                    g_qh[(((size_t)(b * HH + h)) * SS + sidx) * DQK + d] = hv;
                } else {
                    const int h = n >> 8, d = n & 255;
                    if (d < NOPE)
                        g_kh[(((size_t)(b * HH + h)) * SS + sidx) * DQK + d] = hv;
                    else
                        g_vth[(((size_t)(b * HH + h)) * VD + (d - NOPE)) * SS + sidx] = hv;
                }
            }
        }
    }
}

// ---------------------------------------------------------------------------
// RoPE (fp16 in/out)
// ---------------------------------------------------------------------------
__global__ void rope_kernel(const float* __restrict__ PE,
                            const float* __restrict__ cosb,
                            const float* __restrict__ sinb) {
    int tt = blockIdx.x * blockDim.x + threadIdx.x;
    if (tt >= BB * SS * 32) return;
    int i = tt & 31;
    int bs = tt >> 5;
    int b = bs / SS, s = bs % SS;

    float c  = cosb[(size_t)bs * ROPE + i];
    float sn = sinb[(size_t)bs * ROPE + i];

    float p1 = PE[(size_t)bs * ROPE + i];
    float p2 = PE[(size_t)bs * ROPE + i + 32];
    unsigned short k1 = __half_as_ushort(__float2half_rn(p1 * c - p2 * sn));
    unsigned short k2 = __half_as_ushort(__float2half_rn(p2 * c + p1 * sn));

#pragma unroll
    for (int h = 0; h < HH; h++) {
        size_t base = (((size_t)(b * HH + h)) * SS + s) * DQK + NOPE;
        float x1 = __half2float(__ushort_as_half(g_qh[base + i]));
        float x2 = __half2float(__ushort_as_half(g_qh[base + i + 32]));
        g_qh[base + i]      = __half_as_ushort(__float2half_rn(x1 * c - x2 * sn));
        g_qh[base + i + 32] = __half_as_ushort(__float2half_rn(x2 * c + x1 * sn));
        g_kh[base + i]      = k1;
        g_kh[base + i + 32] = k2;
    }
}

// ---------------------------------------------------------------------------
// Flash attention (causal): BQ=256, BK=64, 512 threads (16 warps x m16).
// Pure fp16; K/V double-buffered cp.async; register softmax.
// ---------------------------------------------------------------------------
#define BQF 256
#define QP2 200   // Q/K smem pitch (halfs)
#define VP2 72    // V pitch (halfs)
#define FK_OFF  (BQF*QP2)                  // after sQh
#define FV_OFF  (FK_OFF + 2*64*QP2)
#define FL_SMEM_BYTES ((FV_OFF + 2*128*VP2) * 2)   // 190464 B

extern __shared__ unsigned short fsm2[];

__global__ __launch_bounds__(512, 1) void flash_kernel(float* __restrict__ out) {
    const int qt = gridDim.x - 1 - blockIdx.x;   // heavy CTAs first
    const int h = blockIdx.y, b = blockIdx.z;
    const int tid = threadIdx.x;
    const int w = tid >> 5, lane = tid & 31;
    const int g = lane >> 2, t = lane & 3;
    const int lrow = lane & 15, lc8 = (lane >> 4) << 3;

    const uint32_t uS  = smem_u32(fsm2);
    const uint32_t uQh = uS;

    const int wm = w * 16;                 // warp's q-row slab within block
    const int q0 = qt * BQF;
    const size_t bh = (size_t)(b * HH + h);
    const size_t qgbase = (bh * SS + q0) * DQK;
    const size_t kgbase = bh * SS * DQK;
    const size_t vgbase = bh * VD * SS;

    // copy mappings (1 seg = 16 B = 8 halfs); 512 threads
    const int krow[3] = {(tid + 0) / 24, (tid + 512) / 24, (tid + 1024) / 24};
    const int kseg[3] = {(tid + 0) % 24, (tid + 512) % 24, (tid + 1024) % 24};
    const int vrow[2] = {(tid + 0) >> 3, (tid + 512) >> 3};
    const int vseg[2] = {(tid + 0) & 7, (tid + 512) & 7};

    auto issue_kv = [&](int s, int k0) {
        const uint32_t kb = uS + (FK_OFF + s * 64 * QP2) * 2;
        const uint32_t vb = uS + (FV_OFF + s * 128 * VP2) * 2;
#pragma unroll
        for (int i = 0; i < 3; i++)
            cpasync16(kb + (uint32_t)((krow[i] * QP2 + kseg[i] * 8) * 2),
                      g_kh + kgbase + (size_t)(k0 + krow[i]) * DQK + kseg[i] * 8);
#pragma unroll
        for (int i = 0; i < 2; i++)
            cpasync16(vb + (uint32_t)((vrow[i] * VP2 + vseg[i] * 8) * 2),
                      g_vth + vgbase + (size_t)vrow[i] * SS + k0 + vseg[i] * 8);
    };

    // group 0: Q tile (256 rows x 24 segs) + stage-0 K/V
#pragma unroll
    for (int i = 0; i < 12; i++) {
        int idx = tid + i * 512;
        int r = idx / 24, sg = idx % 24;
        cpasync16(uS + (uint32_t)((r * QP2 + sg * 8) * 2),
                  g_qh + qgbase + (size_t)r * DQK + sg * 8);
    }
    issue_kv(0, 0);
    CP_COMMIT();

    const int r0g = q0 + wm + g;
    const int r1g = r0g + 8;

    float po[16][4] = {};
    float m0 = -1e30f, m1 = -1e30f, l0 = 0.f, l1 = 0.f;

    const int nkt = 4 * (qt + 1);
    for (int kt = 0; kt < nkt; kt++) {
        const int k0 = kt * 64;
        const int s = kt & 1;
        if (kt + 1 < nkt) {
            issue_kv(s ^ 1, k0 + 64);
            CP_COMMIT();
            CP_WAIT(1);
        } else {
            CP_WAIT(0);
        }
        __syncthreads();

        if (k0 <= q0 + wm + 15) {
            const uint32_t uKh = uS + (FK_OFF + s * 64 * QP2) * 2;
            const uint32_t uVh = uS + (FV_OFF + s * 128 * VP2) * 2;

            // ---- scores ----
            float sc[8][4] = {};
#pragma unroll
            for (int kk = 0; kk < 12; kk++) {
                const int kb = kk << 4;
                uint32_t ah[4];
                ldsm4(ah, uQh + (uint32_t)(((wm + lrow) * QP2 + kb + lc8) * 2));
#pragma unroll
                for (int p = 0; p < 4; p++) {
                    uint32_t b4h[4];
                    ldsm4(b4h, uKh + (uint32_t)(((p * 16 + lrow) * QP2 + kb + lc8) * 2));
                    uint32_t bhe[2] = {b4h[0], b4h[2]}, bho[2] = {b4h[1], b4h[3]};
                    mma16(sc[2 * p],     ah, bhe);
                    mma16(sc[2 * p + 1], ah, bho);
                }
            }

            // ---- mask + scale + register online softmax ----
            const bool needmask = (k0 + 63 > r0g);
            float mx0 = -1e30f, mx1 = -1e30f;
#pragma unroll
            for (int nf = 0; nf < 8; nf++) {
                const int c0 = k0 + nf * 8 + (t << 1);
                if (needmask) {
                    sc[nf][0] = (c0     > r0g) ? -1e30f : sc[nf][0] * SCALE;
                    sc[nf][1] = (c0 + 1 > r0g) ? -1e30f : sc[nf][1] * SCALE;
                    sc[nf][2] = (c0     > r1g) ? -1e30f : sc[nf][2] * SCALE;
                    sc[nf][3] = (c0 + 1 > r1g) ? -1e30f : sc[nf][3] * SCALE;
                } else {
                    sc[nf][0] *= SCALE; sc[nf][1] *= SCALE;
                    sc[nf][2] *= SCALE; sc[nf][3] *= SCALE;
                }
                mx0 = fmaxf(mx0, fmaxf(sc[nf][0], sc[nf][1]));
                mx1 = fmaxf(mx1, fmaxf(sc[nf][2], sc[nf][3]));
            }
            mx0 = fmaxf(mx0, __shfl_xor_sync(0xffffffffu, mx0, 1));
            mx0 = fmaxf(mx0, __shfl_xor_sync(0xffffffffu, mx0, 2));
            mx1 = fmaxf(mx1, __shfl_xor_sync(0xffffffffu, mx1, 1));
            mx1 = fmaxf(mx1, __shfl_xor_sync(0xffffffffu, mx1, 2));
            mx0 = fmaxf(mx0, m0);
            mx1 = fmaxf(mx1, m1);
            const float al0 = __expf(m0 - mx0);
            const float al1 = __expf(m1 - mx1);
            m0 = mx0; m1 = mx1;

            uint32_t pah[4][4];
            float s0 = 0.f, s1 = 0.f;
#pragma unroll
            for (int j = 0; j < 4; j++) {
                float p00 = __expf(sc[2 * j][0] - mx0), p01 = __expf(sc[2 * j][1] - mx0);
                float p10 = __expf(sc[2 * j][2] - mx1), p11 = __expf(sc[2 * j][3] - mx1);
                float q00 = __expf(sc[2 * j + 1][0] - mx0), q01 = __expf(sc[2 * j + 1][1] - mx0);
                float q10 = __expf(sc[2 * j + 1][2] - mx1), q11 = __expf(sc[2 * j + 1][3] - mx1);
                s0 += p00 + p01 + q00 + q01;
                s1 += p10 + p11 + q10 + q11;
                pah[j][0] = pack2(p00, p01);
                pah[j][1] = pack2(p10, p11);
                pah[j][2] = pack2(q00, q01);
                pah[j][3] = pack2(q10, q11);
            }
            s0 += __shfl_xor_sync(0xffffffffu, s0, 1);
            s0 += __shfl_xor_sync(0xffffffffu, s0, 2);
            s1 += __shfl_xor_sync(0xffffffffu, s1, 1);
            s1 += __shfl_xor_sync(0xffffffffu, s1, 2);
            l0 = l0 * al0 + s0;
            l1 = l1 * al1 + s1;

            // ---- PV ----
#pragma unroll
            for (int nf = 0; nf < 16; nf++) {
                po[nf][0] *= al0; po[nf][1] *= al0;
                po[nf][2] *= al1; po[nf][3] *= al1;
            }
#pragma unroll
            for (int j = 0; j < 4; j++) {
                const int kb = j << 4;
#pragma unroll
                for (int p = 0; p < 8; p++) {
                    uint32_t b4h[4];
                    ldsm4(b4h, uVh + (uint32_t)(((p * 16 + lrow) * VP2 + kb + lc8) * 2));
                    uint32_t bhe[2] = {b4h[0], b4h[2]}, bho[2] = {b4h[1], b4h[3]};
                    mma16(po[2 * p],     pah[j], bhe);
                    mma16(po[2 * p + 1], pah[j], bho);
                }
            }
        }
        __syncthreads();
    }

    // epilogue
    {
        const float iv0 = 1.f / l0;
        const float iv1 = 1.f / l1;
        const size_t ob0 = (((size_t)b * SS + r0g) * HH + h) * VD;
        const size_t ob1 = (((size_t)b * SS + r1g) * HH + h) * VD;
#pragma unroll
        for (int nf = 0; nf < 16; nf++) {
            const int cl = nf * 8 + (t << 1);
            *(float2*)&out[ob0 + cl] = make_float2(po[nf][0] * iv0, po[nf][1] * iv0);
            *(float2*)&out[ob1 + cl] = make_float2(po[nf][2] * iv1, po[nf][3] * iv1);
        }
    }
}

// ---------------------------------------------------------------------------
extern "C" void kernel_launch(void* const* d_in, const int* in_sizes, int n_in,
                              void* d_out, int out_size) {
    const float* Q    = (const float*)d_in[0];
    const float* KV   = (const float*)d_in[1];
    const float* PE   = (const float*)d_in[2];
    const float* WUQ  = (const float*)d_in[3];
    const float* WUKV = (const float*)d_in[4];
    const float* cosb = (const float*)d_in[5];
    const float* sinb = (const float*)d_in[6];
    float* out = (float*)d_out;
    (void)in_sizes; (void)n_in; (void)out_size;

    cudaFuncSetAttribute(flash_kernel, cudaFuncAttributeMaxDynamicSharedMemorySize,
                         FL_SMEM_BYTES);
    cudaFuncSetAttribute(gemm_mma_kernel<0>, cudaFuncAttributeMaxDynamicSharedMemorySize,
                         GSMEM_TOTAL);
    cudaFuncSetAttribute(gemm_mma_kernel<1>, cudaFuncAttributeMaxDynamicSharedMemorySize,
                         GSMEM_TOTAL);

    presplit_kernel<0><<<(MM * QR / 4 + 255) / 256, 256>>>(Q,    MM * QR / 4);
    presplit_kernel<1><<<(MM * KVR / 4 + 255) / 256, 256>>>(KV,   MM * KVR / 4);
    presplit_kernel<2><<<(NQ * QR / 4 + 255) / 256, 256>>>(WUQ,  NQ * QR / 4);
    presplit_kernel<3><<<(NKV * KVR / 4 + 255) / 256, 256>>>(WUKV, NKV * KVR / 4);

    dim3 g1(NQ / 128, MM / 128);   // (24, 32)
    gemm_mma_kernel<0><<<g1, 512, GSMEM_TOTAL>>>();

    dim3 g2(NKV / 128, MM / 128);  // (32, 32)
    gemm_mma_kernel<1><<<g2, 512, GSMEM_TOTAL>>>();

    int nrope = BB * SS * 32;
    rope_kernel<<<(nrope + 255) / 256, 256>>>(PE, cosb, sinb);

    dim3 gf(SS / BQF, HH, BB);     // (8, 16, 2)
    flash_kernel<<<gf, 512, FL_SMEM_BYTES>>>(out);
}

// round 14
// speedup vs baseline: 1.9267x; 1.9267x over previous
#include <cuda_runtime.h>
#include <cuda_fp16.h>
#include <math.h>
#include <stdint.h>

#define BB 2
#define SS 2048
#define HH 16
#define NOPE 128
#define ROPE 64
#define VD 128
#define DQK 192           // NOPE + ROPE
#define QR 1536
#define KVR 512
#define NQ (HH*DQK)       // 3072
#define NKV (HH*(NOPE+VD))// 4096
#define MM (BB*SS)        // 4096
#define SCALE 0.07216878364870323f  // 1/sqrt(192)

// pure fp16 storage
__device__ __align__(256) unsigned short g_qh[(size_t)BB*HH*SS*DQK];   // [b,h,s,192]
__device__ __align__(256) unsigned short g_kh[(size_t)BB*HH*SS*DQK];   // [b,h,s,192]
__device__ __align__(256) unsigned short g_vth[(size_t)BB*HH*VD*SS];   // [b,h,d,s]
__device__ __align__(256) unsigned short g_qs_h[(size_t)MM*QR];
__device__ __align__(256) unsigned short g_kvs_h[(size_t)MM*KVR];
__device__ __align__(256) unsigned short g_wuq_h[(size_t)NQ*QR];
__device__ __align__(256) unsigned short g_wukv_h[(size_t)NKV*KVR];

// ---------------------------------------------------------------------------
// helpers
// ---------------------------------------------------------------------------
__device__ __forceinline__ uint32_t smem_u32(const void* p) {
    uint32_t a;
    asm("{ .reg .u64 t; cvta.to.shared.u64 t, %1; cvt.u32.u64 %0, t; }" : "=r"(a) : "l"(p));
    return a;
}
__device__ __forceinline__ void ldsm4(uint32_t* r, uint32_t addr) {
    asm volatile("ldmatrix.sync.aligned.m8n8.x4.shared.b16 {%0,%1,%2,%3}, [%4];"
                 : "=r"(r[0]), "=r"(r[1]), "=r"(r[2]), "=r"(r[3]) : "r"(addr));
}
__device__ __forceinline__ void mma16(float* c, const uint32_t* a, const uint32_t* b) {
    asm volatile("mma.sync.aligned.m16n8k16.row.col.f32.f16.f16.f32 "
                 "{%0,%1,%2,%3}, {%4,%5,%6,%7}, {%8,%9}, {%0,%1,%2,%3};"
                 : "+f"(c[0]), "+f"(c[1]), "+f"(c[2]), "+f"(c[3])
                 : "r"(a[0]), "r"(a[1]), "r"(a[2]), "r"(a[3]), "r"(b[0]), "r"(b[1]));
}
__device__ __forceinline__ void cpasync16(uint32_t sdst, const void* gsrc) {
    asm volatile("cp.async.cg.shared.global [%0], [%1], 16;" :: "r"(sdst), "l"(gsrc));
}
#define CP_COMMIT() asm volatile("cp.async.commit_group;" ::: "memory")
#define CP_WAIT(N)  asm volatile("cp.async.wait_group %0;" :: "n"(N) : "memory")

__device__ __forceinline__ uint32_t pack2(float x, float y) {
    __half2 h = __floats2half2_rn(x, y);
    return *(uint32_t*)&h;
}

// ---------------------------------------------------------------------------
// fused presplit: float -> fp16 for all four operand arrays in one launch
// ---------------------------------------------------------------------------
#define N4_Q   (MM*QR/4)
#define N4_KV  (MM*KVR/4)
#define N4_WQ  (NQ*QR/4)
#define N4_WKV (NKV*KVR/4)
#define N4_TOT (N4_Q + N4_KV + N4_WQ + N4_WKV)

__global__ void presplit_all_kernel(const float* __restrict__ Q,
                                    const float* __restrict__ KV,
                                    const float* __restrict__ WUQ,
                                    const float* __restrict__ WUKV) {
    int i = blockIdx.x * blockDim.x + threadIdx.x;
    if (i >= N4_TOT) return;
    const float* src;
    unsigned short* dst;
    int j = i;
    if (j < N4_Q)                { src = Q;    dst = g_qs_h; }
    else if ((j -= N4_Q)  < N4_KV) { src = KV;   dst = g_kvs_h; }
    else if ((j -= N4_KV) < N4_WQ) { src = WUQ;  dst = g_wuq_h; }
    else { j -= N4_WQ;             src = WUKV; dst = g_wukv_h; }
    float4 v = ((const float4*)src)[j];
    ushort4 hh;
    hh.x = __half_as_ushort(__float2half_rn(v.x));
    hh.y = __half_as_ushort(__float2half_rn(v.y));
    hh.z = __half_as_ushort(__float2half_rn(v.z));
    hh.w = __half_as_ushort(__float2half_rn(v.w));
    ((ushort4*)dst)[j] = hh;
}

// ---------------------------------------------------------------------------
// GEMM (pure fp16): CTA 128x128, 512 thr (16 warps 4m x 4n), Kc=64,
// 2-stage cp.async pipeline.
// ---------------------------------------------------------------------------
#define GP 72                 // smem row pitch (halfs) for Kc=64
#define GTILE (128*GP)
#define GSTAGE (2*GTILE*2)    // bytes per stage (Ah, Wh) = 36864
#define GSMEM_TOTAL (2*GSTAGE)

extern __shared__ char gsm[];

template<int MODE>
__global__ __launch_bounds__(512) void gemm_mma_kernel() {
    const unsigned short* Ah = (MODE == 0) ? g_qs_h : g_kvs_h;
    const unsigned short* Wh = (MODE == 0) ? g_wuq_h : g_wukv_h;
    const int K = (MODE == 0) ? QR : KVR;

    const int tid = threadIdx.x;
    const int w = tid >> 5, lane = tid & 31;
    const int g = lane >> 2, t = lane & 3;
    const int lrow = lane & 15, lc8 = (lane >> 4) << 3;
    const int bm = blockIdx.y * 128, bn = blockIdx.x * 128;
    const int mw = (w >> 2) * 32, nw = (w & 3) * 32;
    const uint32_t uS = smem_u32(gsm);

    // copy mapping: 128 rows x 8 segs = 1024 segs per tile; 2 per thread per tile
    int rr[2], rf[2];
#pragma unroll
    for (int i = 0; i < 2; i++) {
        int idx = tid + i * 512;
        rr[i] = idx >> 3; rf[i] = (idx & 7) << 3;   // seg start in halfs
    }

    auto issue_stage = [&](int s, int k0) {
        const uint32_t base = uS + s * GSTAGE;
#pragma unroll
        for (int i = 0; i < 2; i++) {
            const uint32_t off = (uint32_t)((rr[i] * GP + rf[i]) * 2);
            cpasync16(base + off,             Ah + (size_t)(bm + rr[i]) * K + k0 + rf[i]);
            cpasync16(base + GTILE * 2 + off, Wh + (size_t)(bn + rr[i]) * K + k0 + rf[i]);
        }
    };

    float c[2][4][4] = {};
    issue_stage(0, 0);
    CP_COMMIT();

    const int nc = K >> 6;   // chunks of 64
    for (int cc = 0; cc < nc; cc++) {
        const int s = cc & 1;
        if (cc + 1 < nc) {
            issue_stage(s ^ 1, (cc + 1) << 6);
            CP_COMMIT();
            CP_WAIT(1);
        } else {
            CP_WAIT(0);
        }
        __syncthreads();

        const uint32_t uAh = uS + s * GSTAGE;
        const uint32_t uWh = uAh + GTILE * 2;
#pragma unroll
        for (int kk = 0; kk < 4; kk++) {
            const int kb = kk << 4;
            uint32_t ah[2][4];
#pragma unroll
            for (int mf = 0; mf < 2; mf++) {
                uint32_t off = (uint32_t)(((mw + mf * 16 + lrow) * GP + kb + lc8) * 2);
                ldsm4(ah[mf], uAh + off);
            }
#pragma unroll
            for (int p = 0; p < 2; p++) {
                uint32_t off = (uint32_t)(((nw + p * 16 + lrow) * GP + kb + lc8) * 2);
                uint32_t b4h[4];
                ldsm4(b4h, uWh + off);
                uint32_t bhe[2] = {b4h[0], b4h[2]}, bho[2] = {b4h[1], b4h[3]};
#pragma unroll
                for (int mf = 0; mf < 2; mf++) {
                    mma16(c[mf][2 * p],     ah[mf], bhe);
                    mma16(c[mf][2 * p + 1], ah[mf], bho);
                }
            }
        }
        __syncthreads();
    }

    // epilogue
#pragma unroll
    for (int mf = 0; mf < 2; mf++) {
#pragma unroll
        for (int i = 0; i < 4; i++) {
            const int m = bm + mw + mf * 16 + g + ((i >> 1) << 3);
            const int b = m >> 11, sidx = m & 2047;
#pragma unroll
            for (int nf = 0; nf < 4; nf++) {
                const int n = bn + nw + nf * 8 + (t << 1) + (i & 1);
                const unsigned short hv = __half_as_ushort(__float2half_rn(c[mf][nf][i]));
                if (MODE == 0) {
                    const int h = n / DQK, d = n % DQK;
                    g_qh[(((size_t)(b * HH + h)) * SS + sidx) * DQK + d] = hv;
                } else {
                    const int h = n >> 8, d = n & 255;
                    if (d < NOPE)
                        g_kh[(((size_t)(b * HH + h)) * SS + sidx) * DQK + d] = hv;
                    else
                        g_vth[(((size_t)(b * HH + h)) * VD + (d - NOPE)) * SS + sidx] = hv;
                }
            }
        }
    }
}

// ---------------------------------------------------------------------------
// RoPE (fp16 in/out)
// ---------------------------------------------------------------------------
__global__ void rope_kernel(const float* __restrict__ PE,
                            const float* __restrict__ cosb,
                            const float* __restrict__ sinb) {
    int tt = blockIdx.x * blockDim.x + threadIdx.x;
    if (tt >= BB * SS * 32) return;
    int i = tt & 31;
    int bs = tt >> 5;
    int b = bs / SS, s = bs % SS;

    float c  = cosb[(size_t)bs * ROPE + i];
    float sn = sinb[(size_t)bs * ROPE + i];

    float p1 = PE[(size_t)bs * ROPE + i];
    float p2 = PE[(size_t)bs * ROPE + i + 32];
    unsigned short k1 = __half_as_ushort(__float2half_rn(p1 * c - p2 * sn));
    unsigned short k2 = __half_as_ushort(__float2half_rn(p2 * c + p1 * sn));

#pragma unroll
    for (int h = 0; h < HH; h++) {
        size_t base = (((size_t)(b * HH + h)) * SS + s) * DQK + NOPE;
        float x1 = __half2float(__ushort_as_half(g_qh[base + i]));
        float x2 = __half2float(__ushort_as_half(g_qh[base + i + 32]));
        g_qh[base + i]      = __half_as_ushort(__float2half_rn(x1 * c - x2 * sn));
        g_qh[base + i + 32] = __half_as_ushort(__float2half_rn(x2 * c + x1 * sn));
        g_kh[base + i]      = k1;
        g_kh[base + i + 32] = k2;
    }
}

// ---------------------------------------------------------------------------
// Flash attention (causal): BQ=128, BK=64, 256 threads (8 warps x m16).
// Pure fp16; K/V double-buffered cp.async; register softmax.  (R12 config)
// ---------------------------------------------------------------------------
#define QP2 200   // Q/K smem pitch (halfs)
#define VP2 72    // V pitch (halfs)
#define FK_OFF  (128*QP2)                  // after sQh
#define FV_OFF  (FK_OFF + 2*64*QP2)
#define FL_SMEM_BYTES ((FV_OFF + 2*128*VP2) * 2)

extern __shared__ unsigned short fsm2[];

__global__ __launch_bounds__(256, 1) void flash_kernel(float* __restrict__ out) {
    const int qt = gridDim.x - 1 - blockIdx.x;   // heavy CTAs first
    const int h = blockIdx.y, b = blockIdx.z;
    const int tid = threadIdx.x;
    const int w = tid >> 5, lane = tid & 31;
    const int g = lane >> 2, t = lane & 3;
    const int lrow = lane & 15, lc8 = (lane >> 4) << 3;

    const uint32_t uS  = smem_u32(fsm2);
    const uint32_t uQh = uS;

    const int wm = w * 16;
    const int q0 = qt * 128;
    const size_t bh = (size_t)(b * HH + h);
    const size_t qgbase = (bh * SS + q0) * DQK;
    const size_t kgbase = bh * SS * DQK;
    const size_t vgbase = bh * VD * SS;

    const int krow[6] = {(tid + 0) / 24, (tid + 256) / 24, (tid + 512) / 24,
                         (tid + 768) / 24, (tid + 1024) / 24, (tid + 1280) / 24};
    const int kseg[6] = {(tid + 0) % 24, (tid + 256) % 24, (tid + 512) % 24,
                         (tid + 768) % 24, (tid + 1024) % 24, (tid + 1280) % 24};
    const int vrow[4] = {(tid + 0) >> 3, (tid + 256) >> 3, (tid + 512) >> 3, (tid + 768) >> 3};
    const int vseg[4] = {(tid + 0) & 7, (tid + 256) & 7, (tid + 512) & 7, (tid + 768) & 7};

    auto issue_kv = [&](int s, int k0) {
        const uint32_t kb = uS + (FK_OFF + s * 64 * QP2) * 2;
        const uint32_t vb = uS + (FV_OFF + s * 128 * VP2) * 2;
#pragma unroll
        for (int i = 0; i < 6; i++)
            cpasync16(kb + (uint32_t)((krow[i] * QP2 + kseg[i] * 8) * 2),
                      g_kh + kgbase + (size_t)(k0 + krow[i]) * DQK + kseg[i] * 8);
#pragma unroll
        for (int i = 0; i < 4; i++)
            cpasync16(vb + (uint32_t)((vrow[i] * VP2 + vseg[i] * 8) * 2),
                      g_vth + vgbase + (size_t)vrow[i] * SS + k0 + vseg[i] * 8);
    };

    // group 0: Q tile + stage-0 K/V
#pragma unroll
    for (int i = 0; i < 12; i++) {
        int idx = tid + i * 256;
        int r = idx / 24, sg = idx % 24;
        cpasync16(uS + (uint32_t)((r * QP2 + sg * 8) * 2),
                  g_qh + qgbase + (size_t)r * DQK + sg * 8);
    }
    issue_kv(0, 0);
    CP_COMMIT();

    const int r0g = q0 + wm + g;
    const int r1g = r0g + 8;

    float po[16][4] = {};
    float m0 = -1e30f, m1 = -1e30f, l0 = 0.f, l1 = 0.f;

    const int nkt = 2 * (qt + 1);
    for (int kt = 0; kt < nkt; kt++) {
        const int k0 = kt * 64;
        const int s = kt & 1;
        if (kt + 1 < nkt) {
            issue_kv(s ^ 1, k0 + 64);
            CP_COMMIT();
            CP_WAIT(1);
        } else {
            CP_WAIT(0);
        }
        __syncthreads();

        if (k0 <= q0 + wm + 15) {
            const uint32_t uKh = uS + (FK_OFF + s * 64 * QP2) * 2;
            const uint32_t uVh = uS + (FV_OFF + s * 128 * VP2) * 2;

            // ---- scores ----
            float sc[8][4] = {};
#pragma unroll
            for (int kk = 0; kk < 12; kk++) {
                const int kb = kk << 4;
                uint32_t ah[4];
                ldsm4(ah, uQh + (uint32_t)(((wm + lrow) * QP2 + kb + lc8) * 2));
#pragma unroll
                for (int p = 0; p < 4; p++) {
                    uint32_t b4h[4];
                    ldsm4(b4h, uKh + (uint32_t)(((p * 16 + lrow) * QP2 + kb + lc8) * 2));
                    uint32_t bhe[2] = {b4h[0], b4h[2]}, bho[2] = {b4h[1], b4h[3]};
                    mma16(sc[2 * p],     ah, bhe);
                    mma16(sc[2 * p + 1], ah, bho);
                }
            }

            // ---- mask + scale + register online softmax ----
            const bool needmask = (k0 + 63 > r0g);
            float mx0 = -1e30f, mx1 = -1e30f;
#pragma unroll
            for (int nf = 0; nf < 8; nf++) {
                const int c0 = k0 + nf * 8 + (t << 1);
                if (needmask) {
                    sc[nf][0] = (c0     > r0g) ? -1e30f : sc[nf][0] * SCALE;
                    sc[nf][1] = (c0 + 1 > r0g) ? -1e30f : sc[nf][1] * SCALE;
                    sc[nf][2] = (c0     > r1g) ? -1e30f : sc[nf][2] * SCALE;
                    sc[nf][3] = (c0 + 1 > r1g) ? -1e30f : sc[nf][3] * SCALE;
                } else {
                    sc[nf][0] *= SCALE; sc[nf][1] *= SCALE;
                    sc[nf][2] *= SCALE; sc[nf][3] *= SCALE;
                }
                mx0 = fmaxf(mx0, fmaxf(sc[nf][0], sc[nf][1]));
                mx1 = fmaxf(mx1, fmaxf(sc[nf][2], sc[nf][3]));
            }
            mx0 = fmaxf(mx0, __shfl_xor_sync(0xffffffffu, mx0, 1));
            mx0 = fmaxf(mx0, __shfl_xor_sync(0xffffffffu, mx0, 2));
            mx1 = fmaxf(mx1, __shfl_xor_sync(0xffffffffu, mx1, 1));
            mx1 = fmaxf(mx1, __shfl_xor_sync(0xffffffffu, mx1, 2));
            mx0 = fmaxf(mx0, m0);
            mx1 = fmaxf(mx1, m1);
            const float al0 = __expf(m0 - mx0);
            const float al1 = __expf(m1 - mx1);
            m0 = mx0; m1 = mx1;

            uint32_t pah[4][4];
            float s0 = 0.f, s1 = 0.f;
#pragma unroll
            for (int j = 0; j < 4; j++) {
                float p00 = __expf(sc[2 * j][0] - mx0), p01 = __expf(sc[2 * j][1] - mx0);
                float p10 = __expf(sc[2 * j][2] - mx1), p11 = __expf(sc[2 * j][3] - mx1);
                float q00 = __expf(sc[2 * j + 1][0] - mx0), q01 = __expf(sc[2 * j + 1][1] - mx0);
                float q10 = __expf(sc[2 * j + 1][2] - mx1), q11 = __expf(sc[2 * j + 1][3] - mx1);
                s0 += p00 + p01 + q00 + q01;
                s1 += p10 + p11 + q10 + q11;
                pah[j][0] = pack2(p00, p01);
                pah[j][1] = pack2(p10, p11);
                pah[j][2] = pack2(q00, q01);
                pah[j][3] = pack2(q10, q11);
            }
            s0 += __shfl_xor_sync(0xffffffffu, s0, 1);
            s0 += __shfl_xor_sync(0xffffffffu, s0, 2);
            s1 += __shfl_xor_sync(0xffffffffu, s1, 1);
            s1 += __shfl_xor_sync(0xffffffffu, s1, 2);
            l0 = l0 * al0 + s0;
            l1 = l1 * al1 + s1;

            // ---- PV ----
#pragma unroll
            for (int nf = 0; nf < 16; nf++) {
                po[nf][0] *= al0; po[nf][1] *= al0;
                po[nf][2] *= al1; po[nf][3] *= al1;
            }
#pragma unroll
            for (int j = 0; j < 4; j++) {
                const int kb = j << 4;
#pragma unroll
                for (int p = 0; p < 8; p++) {
                    uint32_t b4h[4];
                    ldsm4(b4h, uVh + (uint32_t)(((p * 16 + lrow) * VP2 + kb + lc8) * 2));
                    uint32_t bhe[2] = {b4h[0], b4h[2]}, bho[2] = {b4h[1], b4h[3]};
                    mma16(po[2 * p],     pah[j], bhe);
                    mma16(po[2 * p + 1], pah[j], bho);
                }
            }
        }
        __syncthreads();
    }

    // epilogue
    {
        const float iv0 = 1.f / l0;
        const float iv1 = 1.f / l1;
        const size_t ob0 = (((size_t)b * SS + r0g) * HH + h) * VD;
        const size_t ob1 = (((size_t)b * SS + r1g) * HH + h) * VD;
#pragma unroll
        for (int nf = 0; nf < 16; nf++) {
            const int cl = nf * 8 + (t << 1);
            *(float2*)&out[ob0 + cl] = make_float2(po[nf][0] * iv0, po[nf][1] * iv0);
            *(float2*)&out[ob1 + cl] = make_float2(po[nf][2] * iv1, po[nf][3] * iv1);
        }
    }
}

// ---------------------------------------------------------------------------
extern "C" void kernel_launch(void* const* d_in, const int* in_sizes, int n_in,
                              void* d_out, int out_size) {
    const float* Q    = (const float*)d_in[0];
    const float* KV   = (const float*)d_in[1];
    const float* PE   = (const float*)d_in[2];
    const float* WUQ  = (const float*)d_in[3];
    const float* WUKV = (const float*)d_in[4];
    const float* cosb = (const float*)d_in[5];
    const float* sinb = (const float*)d_in[6];
    float* out = (float*)d_out;
    (void)in_sizes; (void)n_in; (void)out_size;

    cudaFuncSetAttribute(flash_kernel, cudaFuncAttributeMaxDynamicSharedMemorySize,
                         FL_SMEM_BYTES);
    cudaFuncSetAttribute(gemm_mma_kernel<0>, cudaFuncAttributeMaxDynamicSharedMemorySize,
                         GSMEM_TOTAL);
    cudaFuncSetAttribute(gemm_mma_kernel<1>, cudaFuncAttributeMaxDynamicSharedMemorySize,
                         GSMEM_TOTAL);

    presplit_all_kernel<<<(N4_TOT + 255) / 256, 256>>>(Q, KV, WUQ, WUKV);

    dim3 g1(NQ / 128, MM / 128);   // (24, 32)
    gemm_mma_kernel<0><<<g1, 512, GSMEM_TOTAL>>>();

    dim3 g2(NKV / 128, MM / 128);  // (32, 32)
    gemm_mma_kernel<1><<<g2, 512, GSMEM_TOTAL>>>();

    int nrope = BB * SS * 32;
    rope_kernel<<<(nrope + 255) / 256, 256>>>(PE, cosb, sinb);

    dim3 gf(SS / 128, HH, BB);     // (32, 16, 2)
    flash_kernel<<<gf, 256, FL_SMEM_BYTES>>>(out);
}